// round 3
// baseline (speedup 1.0000x reference)
#include <cuda_runtime.h>
#include <math.h>
#include <stdint.h>

// Problem constants
#define T_   12
#define B_   16
#define N_   2048
#define D_   128
#define F_   1536   // T_*D_
#define KTOP 5
#define NEG_SLOPE 0.01f

// Scratch (device globals — allocation-free per harness rules)
__device__ float g_hi[(size_t)B_ * N_ * F_];    // tf32-rounded hi part of normalized x
__device__ float g_lo[(size_t)B_ * N_ * F_];    // tf32-rounded residual (lo part)
__device__ float g_dist[(size_t)B_ * N_ * N_];  // Gram matrix [B, N, N]

// ---------------------------------------------------------------------------
__device__ __forceinline__ float tf32_round(float x) {
    uint32_t u;
    asm("cvt.rna.tf32.f32 %0, %1;" : "=r"(u) : "f"(x));
    return __uint_as_float(u);
}

#define CP_ASYNC16(dst, src) \
    asm volatile("cp.async.cg.shared.global [%0], [%1], 16;" :: "r"(dst), "l"(src))
#define CP_COMMIT() asm volatile("cp.async.commit_group;")
#define CP_WAIT1()  asm volatile("cp.async.wait_group 1;")
#define CP_WAIT0()  asm volatile("cp.async.wait_group 0;")

#define MMA_TF32(acc, a0, a1, a2, a3, b0, b1)                                  \
    asm volatile(                                                              \
        "mma.sync.aligned.m16n8k8.row.col.f32.tf32.tf32.f32 "                  \
        "{%0,%1,%2,%3}, {%4,%5,%6,%7}, {%8,%9}, {%0,%1,%2,%3};"                \
        : "+f"(acc[0]), "+f"(acc[1]), "+f"(acc[2]), "+f"(acc[3])               \
        : "r"(a0), "r"(a1), "r"(a2), "r"(a3), "r"(b0), "r"(b1))

// ---------------------------------------------------------------------------
// K1: gather x[t,b,n,d] -> xf[b,n,t*D+d], row-normalize, split hi/lo (tf32x3)
// ---------------------------------------------------------------------------
__global__ __launch_bounds__(256) void pack_norm_kernel(const float* __restrict__ x) {
    int n = blockIdx.x, b = blockIdx.y, tid = threadIdx.x;
    float vals[6];
    float ss = 0.f;
#pragma unroll
    for (int j = 0; j < 6; j++) {
        int idx = tid + j * 256;
        int t = idx >> 7, d = idx & 127;
        float v = x[(((size_t)t * B_ + b) * N_ + n) * D_ + d];
        vals[j] = v;
        ss += v * v;
    }
    __shared__ float red[256];
    red[tid] = ss;
    __syncthreads();
    for (int s = 128; s > 0; s >>= 1) {
        if (tid < s) red[tid] += red[tid + s];
        __syncthreads();
    }
    float r = rsqrtf(red[0]);
    size_t base = ((size_t)b * N_ + n) * F_;
#pragma unroll
    for (int j = 0; j < 6; j++) {
        float v  = vals[j] * r;
        float hi = tf32_round(v);
        float lo = tf32_round(v - hi);
        g_hi[base + tid + j * 256] = hi;
        g_lo[base + tid + j * 256] = lo;
    }
}

// ---------------------------------------------------------------------------
// K2: batched symmetric Gram via tf32x3 mma.sync (m16n8k8)
// BM=BN=128, BK=16, 256 thr = 8 warps (2x4), warp tile 64x32.
// dist = Hi*Hi^T + Hi*Lo^T + Lo*Hi^T   (lo*lo dropped, ~1e-10)
// Upper-triangular 128x128 tile pairs only, mirrored on write.
// ---------------------------------------------------------------------------
#define SPAD 20                       // 16 data + 4 pad floats per smem row
#define TILE_F (128 * SPAD)           // floats per tile buffer
#define TILE_BYTES (TILE_F * 4)

extern __shared__ float dynsmem[];    // [AH0 AH1 AL0 AL1 BH0 BH1 BL0 BL1]

__global__ __launch_bounds__(256, 2) void gemm_sym_tc_kernel() {
    const int NBLK = N_ / 128;
    int p = blockIdx.x, b = blockIdx.y;
    int bi = 0, rem = p;
    while (rem >= NBLK - bi) { rem -= NBLK - bi; bi++; }
    int bj = bi + rem;

    size_t rowA = (size_t)b * N_ * F_ + (size_t)bi * 128 * F_;
    size_t rowB = (size_t)b * N_ * F_ + (size_t)bj * 128 * F_;
    const float* AH = g_hi + rowA;
    const float* AL = g_lo + rowA;
    const float* BH = g_hi + rowB;
    const float* BL = g_lo + rowB;

    int tid = threadIdx.x;
    int lane = tid & 31, warp = tid >> 5;
    int warp_row = warp & 1;   // 64-row slab
    int warp_col = warp >> 1;  // 32-col slab
    int qrow = lane >> 2;      // 0..7
    int qcol = lane & 3;       // 0..3

    // cp.async coords: 2 float4 per array per thread
    int r0 = tid >> 2, c0 = (tid & 3) << 2;
    int r1 = (tid + 256) >> 2, c1 = c0;  // (f&3) identical for f and f+256

    uint32_t sbase = (uint32_t)__cvta_generic_to_shared(dynsmem);

    float acc[4][4][4];
#pragma unroll
    for (int mi = 0; mi < 4; mi++)
#pragma unroll
        for (int ni = 0; ni < 4; ni++)
#pragma unroll
            for (int r = 0; r < 4; r++) acc[mi][ni][r] = 0.f;

    auto load_tile = [&](int buf, int k0) {
        const float* gsrc[4] = {AH, AL, BH, BL};
#pragma unroll
        for (int a = 0; a < 4; a++) {
            uint32_t s = sbase + (uint32_t)(a * 2 + buf) * TILE_BYTES;
            CP_ASYNC16(s + (r0 * SPAD + c0) * 4, gsrc[a] + (size_t)r0 * F_ + k0 + c0);
            CP_ASYNC16(s + (r1 * SPAD + c1) * 4, gsrc[a] + (size_t)r1 * F_ + k0 + c1);
        }
    };

    const int KITERS = F_ / 16;  // 96
    load_tile(0, 0);
    CP_COMMIT();

    for (int it = 0; it < KITERS; it++) {
        if (it + 1 < KITERS) {
            load_tile((it + 1) & 1, (it + 1) * 16);
            CP_COMMIT();
            CP_WAIT1();
        } else {
            CP_WAIT0();
        }
        __syncthreads();

        int buf = it & 1;
        const float* ah = dynsmem + (0 * 2 + buf) * TILE_F;
        const float* al = dynsmem + (1 * 2 + buf) * TILE_F;
        const float* bh = dynsmem + (2 * 2 + buf) * TILE_F;
        const float* bl = dynsmem + (3 * 2 + buf) * TILE_F;

#pragma unroll
        for (int kc = 0; kc < 16; kc += 8) {
            // --- A_hi and B_hi fragments; hi*hi ---
            uint32_t a_hi[4][4];
#pragma unroll
            for (int mi = 0; mi < 4; mi++) {
                int rb = warp_row * 64 + mi * 16 + qrow;
                int cb = kc + qcol;
                a_hi[mi][0] = __float_as_uint(ah[rb * SPAD + cb]);
                a_hi[mi][1] = __float_as_uint(ah[(rb + 8) * SPAD + cb]);
                a_hi[mi][2] = __float_as_uint(ah[rb * SPAD + cb + 4]);
                a_hi[mi][3] = __float_as_uint(ah[(rb + 8) * SPAD + cb + 4]);
            }
            uint32_t b_hi[4][2];
#pragma unroll
            for (int ni = 0; ni < 4; ni++) {
                int nb = warp_col * 32 + ni * 8 + qrow;
                b_hi[ni][0] = __float_as_uint(bh[nb * SPAD + kc + qcol]);
                b_hi[ni][1] = __float_as_uint(bh[nb * SPAD + kc + 4 + qcol]);
            }
#pragma unroll
            for (int mi = 0; mi < 4; mi++)
#pragma unroll
                for (int ni = 0; ni < 4; ni++)
                    MMA_TF32(acc[mi][ni], a_hi[mi][0], a_hi[mi][1], a_hi[mi][2],
                             a_hi[mi][3], b_hi[ni][0], b_hi[ni][1]);

            // --- B_lo fragments; hi*lo (b_lo dies after this) ---
            {
                uint32_t b_lo[4][2];
#pragma unroll
                for (int ni = 0; ni < 4; ni++) {
                    int nb = warp_col * 32 + ni * 8 + qrow;
                    b_lo[ni][0] = __float_as_uint(bl[nb * SPAD + kc + qcol]);
                    b_lo[ni][1] = __float_as_uint(bl[nb * SPAD + kc + 4 + qcol]);
                }
#pragma unroll
                for (int mi = 0; mi < 4; mi++)
#pragma unroll
                    for (int ni = 0; ni < 4; ni++)
                        MMA_TF32(acc[mi][ni], a_hi[mi][0], a_hi[mi][1], a_hi[mi][2],
                                 a_hi[mi][3], b_lo[ni][0], b_lo[ni][1]);
            }

            // --- A_lo fragments; lo*hi ---
            {
                uint32_t a_lo[4][4];
#pragma unroll
                for (int mi = 0; mi < 4; mi++) {
                    int rb = warp_row * 64 + mi * 16 + qrow;
                    int cb = kc + qcol;
                    a_lo[mi][0] = __float_as_uint(al[rb * SPAD + cb]);
                    a_lo[mi][1] = __float_as_uint(al[(rb + 8) * SPAD + cb]);
                    a_lo[mi][2] = __float_as_uint(al[rb * SPAD + cb + 4]);
                    a_lo[mi][3] = __float_as_uint(al[(rb + 8) * SPAD + cb + 4]);
                }
#pragma unroll
                for (int mi = 0; mi < 4; mi++)
#pragma unroll
                    for (int ni = 0; ni < 4; ni++)
                        MMA_TF32(acc[mi][ni], a_lo[mi][0], a_lo[mi][1], a_lo[mi][2],
                                 a_lo[mi][3], b_hi[ni][0], b_hi[ni][1]);
            }
        }
        __syncthreads();
    }

    // Epilogue: upper tile + mirrored lower tile if off-diagonal
    float* Db = g_dist + (size_t)b * N_ * N_;
#pragma unroll
    for (int mi = 0; mi < 4; mi++) {
        int gi = bi * 128 + warp_row * 64 + mi * 16 + qrow;
#pragma unroll
        for (int ni = 0; ni < 4; ni++) {
            int gj = bj * 128 + warp_col * 32 + ni * 8 + 2 * qcol;
            float2 v01 = make_float2(acc[mi][ni][0], acc[mi][ni][1]);
            float2 v23 = make_float2(acc[mi][ni][2], acc[mi][ni][3]);
            *(float2*)&Db[(size_t)gi * N_ + gj] = v01;
            *(float2*)&Db[(size_t)(gi + 8) * N_ + gj] = v23;
            if (bi != bj) {
                Db[(size_t)gj * N_ + gi] = v01.x;
                Db[(size_t)(gj + 1) * N_ + gi] = v01.y;
                Db[(size_t)gj * N_ + gi + 8] = v23.x;
                Db[(size_t)(gj + 1) * N_ + gi + 8] = v23.y;
            }
        }
    }
}

// ---------------------------------------------------------------------------
// K3: per-row top-5 (lowest-index tie-break) + fused symmetric scatter
// ---------------------------------------------------------------------------
__global__ __launch_bounds__(256) void topk_scatter_kernel(float* __restrict__ out) {
    int i = blockIdx.x, b = blockIdx.y, tid = threadIdx.x;
    const float* drow = g_dist + ((size_t)b * N_ + i) * N_;

    __shared__ float sv[N_];
    __shared__ float rv[256];
    __shared__ int   ri[256];
    __shared__ float selV[KTOP];
    __shared__ int   selI[KTOP];

#pragma unroll
    for (int j = 0; j < N_ / 256; j++) sv[tid + j * 256] = drow[tid + j * 256];
    __syncthreads();

    for (int k = 0; k < KTOP; k++) {
        float bv = -INFINITY;
        int bidx = 0x7fffffff;
#pragma unroll
        for (int j = 0; j < N_ / 256; j++) {
            int idx = tid + j * 256;
            float v = sv[idx];
            if (v > bv) { bv = v; bidx = idx; }
        }
        rv[tid] = bv;
        ri[tid] = bidx;
        __syncthreads();
        for (int s = 128; s > 0; s >>= 1) {
            if (tid < s) {
                float v2 = rv[tid + s];
                int   i2 = ri[tid + s];
                if (v2 > rv[tid] || (v2 == rv[tid] && i2 < ri[tid])) {
                    rv[tid] = v2;
                    ri[tid] = i2;
                }
            }
            __syncthreads();
        }
        if (tid == 0) {
            selV[k] = rv[0];
            selI[k] = ri[0];
            sv[ri[0]] = -INFINITY;
        }
        __syncthreads();
    }

    if (tid < KTOP) {
        float v = selV[tid];
        int   j = selI[tid];
        float w = 0.5f * (v >= 0.f ? v : NEG_SLOPE * v);
        float* ob = out + (size_t)b * N_ * N_;
        atomicAdd(&ob[(size_t)i * N_ + j], w);
        atomicAdd(&ob[(size_t)j * N_ + i], w);
    }
}

// ---------------------------------------------------------------------------
extern "C" void kernel_launch(void* const* d_in, const int* in_sizes, int n_in,
                              void* d_out, int out_size) {
    const float* x = (const float*)d_in[0];
    float* out = (float*)d_out;

    static bool attr_set = false;
    if (!attr_set) {
        cudaFuncSetAttribute(gemm_sym_tc_kernel,
                             cudaFuncAttributeMaxDynamicSharedMemorySize,
                             8 * TILE_BYTES);
        attr_set = true;
    }

    pack_norm_kernel<<<dim3(N_, B_), 256>>>(x);
    gemm_sym_tc_kernel<<<dim3(136, B_), 256, 8 * TILE_BYTES>>>();
    cudaMemsetAsync(d_out, 0, (size_t)out_size * sizeof(float), 0);
    topk_scatter_kernel<<<dim3(N_, B_), 256>>>(out);
}

// round 5
// speedup vs baseline: 3.2062x; 3.2062x over previous
#include <cuda_runtime.h>
#include <cuda_fp16.h>
#include <math.h>
#include <stdint.h>

#define T_   12
#define B_   16
#define N_   2048
#define D_   128
#define F_   1536
#define KTOP 5
#define NEG_SLOPE 0.01f

// fp16 2-way split of normalized features + fp32 Gram matrix
__device__ __half g_p1[(size_t)B_ * N_ * F_];   // ~101 MB
__device__ __half g_p2[(size_t)B_ * N_ * F_];   // ~101 MB
__device__ float g_dist[(size_t)B_ * N_ * N_];  // ~268 MB

// ---------------------------------------------------------------------------
__device__ __forceinline__ uint32_t smem_u32(const void* p) {
    uint32_t a;
    asm("{ .reg .u64 t; cvta.to.shared.u64 t, %1; cvt.u32.u64 %0, t; }"
        : "=r"(a) : "l"(p));
    return a;
}
#define CP_ASYNC16(dst, src) \
    asm volatile("cp.async.cg.shared.global [%0], [%1], 16;" :: "r"(dst), "l"(src))
#define CP_COMMIT() asm volatile("cp.async.commit_group;")
#define CP_WAIT(n)  asm volatile("cp.async.wait_group %0;" :: "n"(n))

#define LDSM_X4(r, a)                                                          \
    asm volatile("ldmatrix.sync.aligned.m8n8.x4.shared.b16 {%0,%1,%2,%3}, [%4];" \
                 : "=r"((r)[0]), "=r"((r)[1]), "=r"((r)[2]), "=r"((r)[3])      \
                 : "r"(a))

#define MMA16816(acc, a, b0, b1)                                               \
    asm volatile(                                                              \
        "mma.sync.aligned.m16n8k16.row.col.f32.f16.f16.f32 "                   \
        "{%0,%1,%2,%3}, {%4,%5,%6,%7}, {%8,%9}, {%0,%1,%2,%3};"                \
        : "+f"((acc)[0]), "+f"((acc)[1]), "+f"((acc)[2]), "+f"((acc)[3])       \
        : "r"((a)[0]), "r"((a)[1]), "r"((a)[2]), "r"((a)[3]), "r"(b0), "r"(b1))

#define SW128(x) ((x) ^ (((x) >> 3) & 0x70))

// ---------------------------------------------------------------------------
// K1: gather x[t,b,n,d] -> xf[b,n,t*D+d], normalize, fp16 split h1+h2
// ---------------------------------------------------------------------------
__global__ __launch_bounds__(256) void pack_norm_kernel(const float* __restrict__ x) {
    int n = blockIdx.x, b = blockIdx.y, tid = threadIdx.x;
    float vals[6];
    float ss = 0.f;
#pragma unroll
    for (int j = 0; j < 6; j++) {
        int idx = tid + j * 256;
        int t = idx >> 7, d = idx & 127;
        float v = x[(((size_t)t * B_ + b) * N_ + n) * D_ + d];
        vals[j] = v;
        ss += v * v;
    }
    __shared__ float red[256];
    red[tid] = ss;
    __syncthreads();
    for (int s = 128; s > 0; s >>= 1) {
        if (tid < s) red[tid] += red[tid + s];
        __syncthreads();
    }
    float r = rsqrtf(red[0]);
    size_t base = ((size_t)b * N_ + n) * F_;
#pragma unroll
    for (int j = 0; j < 6; j++) {
        float v = vals[j] * r;
        __half h1 = __float2half_rn(v);
        __half h2 = __float2half_rn(v - __half2float(h1));
        g_p1[base + tid + j * 256] = h1;
        g_p2[base + tid + j * 256] = h2;
    }
}

// ---------------------------------------------------------------------------
// K2: symmetric Gram via fp16x2 split (3 surfaces), mma.sync m16n8k16 +
// ldmatrix, SW128 smem, K=64 stages, cp.async double buffer.
// BM=BN=128, 8 warps (2x4), warp tile 64x32.
// ---------------------------------------------------------------------------
#define NBLK   (N_ / 128)                   // 16
#define NPAIR  (NBLK * (NBLK + 1) / 2)      // 136
#define SK     64                           // k halves per stage (128B rows)
#define NSTG_S (F_ / SK)                    // 24
#define NSURF  3
#define NS     (NSURF * NSTG_S)             // 72
#define TILEB  (128 * 128)                  // 16KB per operand tile
#define STAGEB (2 * TILEB)                  // 32KB per stage

__global__ __launch_bounds__(256, 2) void gemm_fp16_kernel() {
    extern __shared__ __align__(16) unsigned char dynsmem[];
    uint32_t sraw = smem_u32(dynsmem);
    uint32_t bufb = (sraw + 1023) & ~1023u;  // 1KB align for SW128 pattern

    int tid = threadIdx.x, lane = tid & 31, wid = tid >> 5;
    int p = blockIdx.x, b = blockIdx.y;
    int bi = 0, rem = p;
    while (rem >= NBLK - bi) { rem -= NBLK - bi; bi++; }
    int bj = bi + rem;

    size_t rowA = (size_t)b * N_ * F_ + (size_t)bi * 128 * F_;
    size_t rowB = (size_t)b * N_ * F_ + (size_t)bj * 128 * F_;

    int warp_row = wid & 1;   // 64-row slab
    int warp_col = wid >> 1;  // 32-col slab
    int lr = lane & 7, lm = lane >> 3;

    float acc[4][4][4];
#pragma unroll
    for (int mi = 0; mi < 4; mi++)
#pragma unroll
        for (int ni = 0; ni < 4; ni++)
#pragma unroll
            for (int r = 0; r < 4; r++) acc[mi][ni][r] = 0.f;

    // loader: 1024 16B-segments per operand tile; 256 thr x 4 segs
    auto load_stage = [&](int s, int buf) {
        int surf = s / NSTG_S;
        int k0 = (s - surf * NSTG_S) * SK;
        const __half* Ag = (surf == 2) ? g_p2 : g_p1;  // surfaces: (1,1)(1,2)(2,1)
        const __half* Bg = (surf == 1) ? g_p2 : g_p1;
        const __half* Ap = Ag + rowA + k0;
        const __half* Bp = Bg + rowB + k0;
        uint32_t a_s = bufb + (uint32_t)buf * STAGEB;
        uint32_t b_s = a_s + TILEB;
#pragma unroll
        for (int t = 0; t < 4; t++) {
            int q = tid + t * 256;            // 0..1023
            int r = q >> 3, c16 = q & 7;
            uint32_t so = SW128((uint32_t)(q << 4));
            size_t ge = (size_t)r * F_ + c16 * 8;
            CP_ASYNC16(a_s + so, Ap + ge);
            CP_ASYNC16(b_s + so, Bp + ge);
        }
    };

    load_stage(0, 0);
    CP_COMMIT();

#pragma unroll 1
    for (int s = 0; s < NS; s++) {
        if (s + 1 < NS) {
            load_stage(s + 1, (s + 1) & 1);
            CP_COMMIT();
            CP_WAIT(1);
        } else {
            CP_WAIT(0);
        }
        __syncthreads();

        uint32_t a_s = bufb + (uint32_t)(s & 1) * STAGEB;
        uint32_t b_s = a_s + TILEB;

#pragma unroll
        for (int kc = 0; kc < 4; kc++) {
            int kb = kc * 32;  // byte offset of this k16 chunk
            uint32_t afr[4][4];
#pragma unroll
            for (int mi = 0; mi < 4; mi++) {
                int row = warp_row * 64 + mi * 16 + (lm & 1) * 8 + lr;
                int colb = kb + (lm >> 1) * 16;
                LDSM_X4(afr[mi], a_s + SW128((uint32_t)(row * 128 + colb)));
            }
            uint32_t bfr[2][4];
#pragma unroll
            for (int nj = 0; nj < 2; nj++) {
                int row = warp_col * 32 + nj * 16 + (lm >> 1) * 8 + lr;
                int colb = kb + (lm & 1) * 16;
                LDSM_X4(bfr[nj], b_s + SW128((uint32_t)(row * 128 + colb)));
            }
#pragma unroll
            for (int mi = 0; mi < 4; mi++)
#pragma unroll
                for (int ni = 0; ni < 4; ni++)
                    MMA16816(acc[mi][ni], afr[mi],
                             bfr[ni >> 1][(ni & 1) * 2],
                             bfr[ni >> 1][(ni & 1) * 2 + 1]);
        }
        __syncthreads();
    }

    // Epilogue: n offset for ni is (ni>>1)*16 + (ni&1)*8 (ldmatrix pair order)
    float* Db = g_dist + (size_t)b * N_ * N_;
#pragma unroll
    for (int mi = 0; mi < 4; mi++) {
        int gi = bi * 128 + warp_row * 64 + mi * 16 + (lane >> 2);
#pragma unroll
        for (int ni = 0; ni < 4; ni++) {
            int noff = (ni >> 1) * 16 + (ni & 1) * 8;
            int gj = bj * 128 + warp_col * 32 + noff + 2 * (lane & 3);
            float2 v01 = make_float2(acc[mi][ni][0], acc[mi][ni][1]);
            float2 v23 = make_float2(acc[mi][ni][2], acc[mi][ni][3]);
            *(float2*)&Db[(size_t)gi * N_ + gj] = v01;
            *(float2*)&Db[(size_t)(gi + 8) * N_ + gj] = v23;
            if (bi != bj) {
                Db[(size_t)gj * N_ + gi] = v01.x;
                Db[(size_t)(gj + 1) * N_ + gi] = v01.y;
                Db[(size_t)gj * N_ + gi + 8] = v23.x;
                Db[(size_t)(gj + 1) * N_ + gi + 8] = v23.y;
            }
        }
    }
}

// ---------------------------------------------------------------------------
// K3: per-row top-5 (lowest-index tie-break) + fused symmetric scatter
// ---------------------------------------------------------------------------
__global__ __launch_bounds__(256) void topk_scatter_kernel(float* __restrict__ out) {
    int i = blockIdx.x, b = blockIdx.y, tid = threadIdx.x;
    const float* drow = g_dist + ((size_t)b * N_ + i) * N_;

    __shared__ float sv[N_];
    __shared__ float rv[256];
    __shared__ int   ri[256];
    __shared__ float selV[KTOP];
    __shared__ int   selI[KTOP];

#pragma unroll
    for (int j = 0; j < N_ / 256; j++) sv[tid + j * 256] = drow[tid + j * 256];
    __syncthreads();

    for (int k = 0; k < KTOP; k++) {
        float bv = -INFINITY;
        int bidx = 0x7fffffff;
#pragma unroll
        for (int j = 0; j < N_ / 256; j++) {
            int idx = tid + j * 256;
            float v = sv[idx];
            if (v > bv) { bv = v; bidx = idx; }
        }
        rv[tid] = bv;
        ri[tid] = bidx;
        __syncthreads();
        for (int s = 128; s > 0; s >>= 1) {
            if (tid < s) {
                float v2 = rv[tid + s];
                int   i2 = ri[tid + s];
                if (v2 > rv[tid] || (v2 == rv[tid] && i2 < ri[tid])) {
                    rv[tid] = v2;
                    ri[tid] = i2;
                }
            }
            __syncthreads();
        }
        if (tid == 0) {
            selV[k] = rv[0];
            selI[k] = ri[0];
            sv[ri[0]] = -INFINITY;
        }
        __syncthreads();
    }

    if (tid < KTOP) {
        float v = selV[tid];
        int   j = selI[tid];
        float w = 0.5f * (v >= 0.f ? v : NEG_SLOPE * v);
        float* ob = out + (size_t)b * N_ * N_;
        atomicAdd(&ob[(size_t)i * N_ + j], w);
        atomicAdd(&ob[(size_t)j * N_ + i], w);
    }
}

// ---------------------------------------------------------------------------
extern "C" void kernel_launch(void* const* d_in, const int* in_sizes, int n_in,
                              void* d_out, int out_size) {
    const float* x = (const float*)d_in[0];
    float* out = (float*)d_out;

    const int SMEM_DYN = 1024 + 2 * STAGEB;  // pad + 64KB double buffer
    cudaFuncSetAttribute(gemm_fp16_kernel,
                         cudaFuncAttributeMaxDynamicSharedMemorySize, SMEM_DYN);

    pack_norm_kernel<<<dim3(N_, B_), 256>>>(x);
    gemm_fp16_kernel<<<dim3(NPAIR, B_), 256, SMEM_DYN>>>();
    cudaMemsetAsync(d_out, 0, (size_t)out_size * sizeof(float), 0);
    topk_scatter_kernel<<<dim3(N_, B_), 256>>>(out);
}

// round 6
// speedup vs baseline: 4.8720x; 1.5196x over previous
#include <cuda_runtime.h>
#include <cuda_fp16.h>
#include <math.h>
#include <stdint.h>

#define T_   12
#define B_   16
#define N_   2048
#define D_   128
#define F_   1536
#define KTOP 5
#define NEG_SLOPE 0.01f
#define NCAND 8
#define DELTA 1.2e-4f

// fp16 2-way split of normalized features + fp32 Gram matrix
__device__ __half g_p1[(size_t)B_ * N_ * F_];
__device__ __half g_p2[(size_t)B_ * N_ * F_];
__device__ float g_dist[(size_t)B_ * N_ * N_];

// ---------------------------------------------------------------------------
__device__ __forceinline__ uint32_t smem_u32(const void* p) {
    uint32_t a;
    asm("{ .reg .u64 t; cvta.to.shared.u64 t, %1; cvt.u32.u64 %0, t; }"
        : "=r"(a) : "l"(p));
    return a;
}
#define CP_ASYNC16(dst, src) \
    asm volatile("cp.async.cg.shared.global [%0], [%1], 16;" :: "r"(dst), "l"(src))
#define CP_COMMIT() asm volatile("cp.async.commit_group;")
#define CP_WAIT(n)  asm volatile("cp.async.wait_group %0;" :: "n"(n))

#define LDSM_X4(r, a)                                                          \
    asm volatile("ldmatrix.sync.aligned.m8n8.x4.shared.b16 {%0,%1,%2,%3}, [%4];" \
                 : "=r"((r)[0]), "=r"((r)[1]), "=r"((r)[2]), "=r"((r)[3])      \
                 : "r"(a))

#define MMA16816(acc, a, b0, b1)                                               \
    asm volatile(                                                              \
        "mma.sync.aligned.m16n8k16.row.col.f32.f16.f16.f32 "                   \
        "{%0,%1,%2,%3}, {%4,%5,%6,%7}, {%8,%9}, {%0,%1,%2,%3};"                \
        : "+f"((acc)[0]), "+f"((acc)[1]), "+f"((acc)[2]), "+f"((acc)[3])       \
        : "r"((a)[0]), "r"((a)[1]), "r"((a)[2]), "r"((a)[3]), "r"(b0), "r"(b1))

#define SW128(x) ((x) ^ (((x) >> 3) & 0x70))

// orderable float key (bigger = larger float); low word = ~idx (ties -> low idx)
__device__ __forceinline__ unsigned long long mk_key(float v, int idx) {
    unsigned u = __float_as_uint(v);
    u = (u & 0x80000000u) ? ~u : (u | 0x80000000u);
    return ((unsigned long long)u << 32) | (unsigned)(0xFFFFFFFFu - idx);
}
__device__ __forceinline__ float key_val(unsigned long long k) {
    unsigned u = (unsigned)(k >> 32);
    u = (u & 0x80000000u) ? (u & 0x7FFFFFFFu) : ~u;
    return __uint_as_float(u);
}
__device__ __forceinline__ int key_idx(unsigned long long k) {
    return (int)(0xFFFFFFFFu - (unsigned)(k & 0xFFFFFFFFu));
}

// ---------------------------------------------------------------------------
// K1: gather x[t,b,n,d] -> xf[b,n,t*D+d], normalize, fp16 split h1+h2
// ---------------------------------------------------------------------------
__global__ __launch_bounds__(256) void pack_norm_kernel(const float* __restrict__ x) {
    int n = blockIdx.x, b = blockIdx.y, tid = threadIdx.x;
    float vals[6];
    float ss = 0.f;
#pragma unroll
    for (int j = 0; j < 6; j++) {
        int idx = tid + j * 256;
        int t = idx >> 7, d = idx & 127;
        float v = x[(((size_t)t * B_ + b) * N_ + n) * D_ + d];
        vals[j] = v;
        ss += v * v;
    }
    __shared__ float red[256];
    red[tid] = ss;
    __syncthreads();
    for (int s = 128; s > 0; s >>= 1) {
        if (tid < s) red[tid] += red[tid + s];
        __syncthreads();
    }
    float r = rsqrtf(red[0]);
    size_t base = ((size_t)b * N_ + n) * F_;
#pragma unroll
    for (int j = 0; j < 6; j++) {
        float v = vals[j] * r;
        __half h1 = __float2half_rn(v);
        __half h2 = __float2half_rn(v - __half2float(h1));
        g_p1[base + tid + j * 256] = h1;
        g_p2[base + tid + j * 256] = h2;
    }
}

// ---------------------------------------------------------------------------
// K2: symmetric Gram, single surface h1*h1^T. mma.sync m16n8k16 + ldmatrix,
// SW128 smem, K=64 stages, cp.async double buffer. BM=BN=128, 8 warps.
// ---------------------------------------------------------------------------
#define NBLK   (N_ / 128)
#define NPAIR  (NBLK * (NBLK + 1) / 2)   // 136
#define SK     64
#define NS     (F_ / SK)                 // 24
#define TILEB  (128 * 128)
#define STAGEB (2 * TILEB)

__global__ __launch_bounds__(256, 2) void gemm_fp16_kernel() {
    extern __shared__ __align__(16) unsigned char dynsmem[];
    uint32_t sraw = smem_u32(dynsmem);
    uint32_t bufb = (sraw + 1023) & ~1023u;

    int tid = threadIdx.x, lane = tid & 31, wid = tid >> 5;
    int p = blockIdx.x, b = blockIdx.y;
    int bi = 0, rem = p;
    while (rem >= NBLK - bi) { rem -= NBLK - bi; bi++; }
    int bj = bi + rem;

    size_t rowA = (size_t)b * N_ * F_ + (size_t)bi * 128 * F_;
    size_t rowB = (size_t)b * N_ * F_ + (size_t)bj * 128 * F_;

    int warp_row = wid & 1;
    int warp_col = wid >> 1;
    int lr = lane & 7, lm = lane >> 3;

    float acc[4][4][4];
#pragma unroll
    for (int mi = 0; mi < 4; mi++)
#pragma unroll
        for (int ni = 0; ni < 4; ni++)
#pragma unroll
            for (int r = 0; r < 4; r++) acc[mi][ni][r] = 0.f;

    auto load_stage = [&](int s, int buf) {
        int k0 = s * SK;
        const __half* Ap = g_p1 + rowA + k0;
        const __half* Bp = g_p1 + rowB + k0;
        uint32_t a_s = bufb + (uint32_t)buf * STAGEB;
        uint32_t b_s = a_s + TILEB;
#pragma unroll
        for (int t = 0; t < 4; t++) {
            int q = tid + t * 256;
            int r = q >> 3, c16 = q & 7;
            uint32_t so = SW128((uint32_t)(q << 4));
            size_t ge = (size_t)r * F_ + c16 * 8;
            CP_ASYNC16(a_s + so, Ap + ge);
            CP_ASYNC16(b_s + so, Bp + ge);
        }
    };

    load_stage(0, 0);
    CP_COMMIT();

#pragma unroll 1
    for (int s = 0; s < NS; s++) {
        if (s + 1 < NS) {
            load_stage(s + 1, (s + 1) & 1);
            CP_COMMIT();
            CP_WAIT(1);
        } else {
            CP_WAIT(0);
        }
        __syncthreads();

        uint32_t a_s = bufb + (uint32_t)(s & 1) * STAGEB;
        uint32_t b_s = a_s + TILEB;

#pragma unroll
        for (int kc = 0; kc < 4; kc++) {
            int kb = kc * 32;
            uint32_t afr[4][4];
#pragma unroll
            for (int mi = 0; mi < 4; mi++) {
                int row = warp_row * 64 + mi * 16 + (lm & 1) * 8 + lr;
                int colb = kb + (lm >> 1) * 16;
                LDSM_X4(afr[mi], a_s + SW128((uint32_t)(row * 128 + colb)));
            }
            uint32_t bfr[2][4];
#pragma unroll
            for (int nj = 0; nj < 2; nj++) {
                int row = warp_col * 32 + nj * 16 + (lm >> 1) * 8 + lr;
                int colb = kb + (lm & 1) * 16;
                LDSM_X4(bfr[nj], b_s + SW128((uint32_t)(row * 128 + colb)));
            }
#pragma unroll
            for (int mi = 0; mi < 4; mi++)
#pragma unroll
                for (int ni = 0; ni < 4; ni++)
                    MMA16816(acc[mi][ni], afr[mi],
                             bfr[ni >> 1][(ni & 1) * 2],
                             bfr[ni >> 1][(ni & 1) * 2 + 1]);
        }
        __syncthreads();
    }

    float* Db = g_dist + (size_t)b * N_ * N_;
#pragma unroll
    for (int mi = 0; mi < 4; mi++) {
        int gi = bi * 128 + warp_row * 64 + mi * 16 + (lane >> 2);
#pragma unroll
        for (int ni = 0; ni < 4; ni++) {
            int noff = (ni >> 1) * 16 + (ni & 1) * 8;
            int gj = bj * 128 + warp_col * 32 + noff + 2 * (lane & 3);
            float2 v01 = make_float2(acc[mi][ni][0], acc[mi][ni][1]);
            float2 v23 = make_float2(acc[mi][ni][2], acc[mi][ni][3]);
            *(float2*)&Db[(size_t)gi * N_ + gj] = v01;
            *(float2*)&Db[(size_t)(gi + 8) * N_ + gj] = v23;
            if (bi != bj) {
                Db[(size_t)gj * N_ + gi] = v01.x;
                Db[(size_t)(gj + 1) * N_ + gi] = v01.y;
                Db[(size_t)gj * N_ + gi + 8] = v23.x;
                Db[(size_t)(gj + 1) * N_ + gi + 8] = v23.y;
            }
        }
    }
}

// ---------------------------------------------------------------------------
// K3: per-row approx top-8 (register-resident, shuffle argmax, exact jax
// tie-break) + margin-gated exact fp32 rescore + symmetric scatter.
// ---------------------------------------------------------------------------
__global__ __launch_bounds__(256) void topk_rescore_scatter(float* __restrict__ out) {
    int i = blockIdx.x, b = blockIdx.y, tid = threadIdx.x;
    int lane = tid & 31, wid = tid >> 5;
    const float* drow = g_dist + ((size_t)b * N_ + i) * N_;

    float v[8];
#pragma unroll
    for (int j = 0; j < 8; j++) v[j] = drow[tid + j * 256];

    __shared__ unsigned long long wbest[8];
    __shared__ unsigned long long winner;
    __shared__ unsigned long long s_key[NCAND];
    __shared__ float s_av[NCAND];
    __shared__ int   s_idx[NCAND];
    __shared__ float s_red[8];

    for (int k = 0; k < NCAND; k++) {
        unsigned long long best = 0;
#pragma unroll
        for (int j = 0; j < 8; j++) {
            unsigned long long key = mk_key(v[j], tid + j * 256);
            best = best > key ? best : key;
        }
#pragma unroll
        for (int o = 16; o; o >>= 1) {
            unsigned long long oth = __shfl_xor_sync(0xffffffffu, best, o);
            best = best > oth ? best : oth;
        }
        if (lane == 0) wbest[wid] = best;
        __syncthreads();
        if (tid == 0) {
            unsigned long long bb = wbest[0];
            for (int w = 1; w < 8; w++) bb = bb > wbest[w] ? bb : wbest[w];
            winner = bb;
            s_key[k] = bb;
            s_idx[k] = key_idx(bb);
            s_av[k] = key_val(bb);
        }
        __syncthreads();
        int widx = key_idx(winner);
        if ((widx & 255) == tid) {
            int slot = widx >> 8;
#pragma unroll
            for (int j = 0; j < 8; j++)
                if (j == slot) v[j] = -INFINITY;
        }
        __syncthreads();
    }

    // margin check: any candidate (other than rank 5 itself) within DELTA of v5?
    float v5 = s_av[4];
    bool need = false;
#pragma unroll
    for (int c = 0; c < NCAND; c++)
        if (c != 4 && fabsf(s_av[c] - v5) < DELTA) need = true;

    if (need) {
        size_t basei = ((size_t)b * N_ + i) * F_;
        float fi[6];
#pragma unroll
        for (int s = 0; s < 6; s++) {
            int e = tid + s * 256;
            fi[s] = __half2float(g_p1[basei + e]) + __half2float(g_p2[basei + e]);
        }
#pragma unroll 1
        for (int c = 0; c < NCAND; c++) {
            if (c != 4 && fabsf(s_av[c] - v5) >= DELTA) continue;
            int j = s_idx[c];
            size_t basej = ((size_t)b * N_ + j) * F_;
            float acc = 0.f;
#pragma unroll
            for (int s = 0; s < 6; s++) {
                int e = tid + s * 256;
                float fj = __half2float(g_p1[basej + e]) + __half2float(g_p2[basej + e]);
                acc = fmaf(fi[s], fj, acc);
            }
#pragma unroll
            for (int o = 16; o; o >>= 1) acc += __shfl_xor_sync(0xffffffffu, acc, o);
            if (lane == 0) s_red[wid] = acc;
            __syncthreads();
            if (tid == 0) {
                float t = 0.f;
                for (int w = 0; w < 8; w++) t += s_red[w];
                s_key[c] = mk_key(t, j);   // exact ordering key; output value stays approx
            }
            __syncthreads();
        }
        if (tid == 0) {  // insertion sort desc by key (nearly sorted)
            for (int a = 1; a < NCAND; a++) {
                unsigned long long kk = s_key[a];
                float av = s_av[a];
                int ix = s_idx[a];
                int q = a - 1;
                while (q >= 0 && s_key[q] < kk) {
                    s_key[q + 1] = s_key[q];
                    s_av[q + 1] = s_av[q];
                    s_idx[q + 1] = s_idx[q];
                    q--;
                }
                s_key[q + 1] = kk;
                s_av[q + 1] = av;
                s_idx[q + 1] = ix;
            }
        }
        __syncthreads();
    }

    if (tid < KTOP) {
        float val = s_av[tid];
        int j = s_idx[tid];
        float w = 0.5f * (val >= 0.f ? val : NEG_SLOPE * val);
        float* ob = out + (size_t)b * N_ * N_;
        atomicAdd(&ob[(size_t)i * N_ + j], w);
        atomicAdd(&ob[(size_t)j * N_ + i], w);
    }
}

// ---------------------------------------------------------------------------
extern "C" void kernel_launch(void* const* d_in, const int* in_sizes, int n_in,
                              void* d_out, int out_size) {
    const float* x = (const float*)d_in[0];
    float* out = (float*)d_out;

    const int SMEM_DYN = 1024 + 2 * STAGEB;
    cudaFuncSetAttribute(gemm_fp16_kernel,
                         cudaFuncAttributeMaxDynamicSharedMemorySize, SMEM_DYN);

    pack_norm_kernel<<<dim3(N_, B_), 256>>>(x);
    gemm_fp16_kernel<<<dim3(NPAIR, B_), 256, SMEM_DYN>>>();
    cudaMemsetAsync(d_out, 0, (size_t)out_size * sizeof(float), 0);
    topk_rescore_scatter<<<dim3(N_, B_), 256>>>(out);
}